// round 7
// baseline (speedup 1.0000x reference)
#include <cuda_runtime.h>

typedef unsigned long long u64;

#define B_  2
#define T_  2560
#define C_  768
#define H_  12
#define HD_ 64
#define M_  (B_*T_)   // 5120

// ---- scratch (static device arrays; no allocation) ----
__device__ float g_Q[B_*H_*T_*HD_];
__device__ float g_K[B_*H_*T_*HD_];
__device__ float g_V[B_*H_*T_*HD_];
__device__ float g_Y[B_*T_*C_];

// ---- packed f32x2 helpers (Blackwell FFMA2) ----
__device__ __forceinline__ u64 fma2(u64 a, u64 b, u64 c) {
    u64 d; asm("fma.rn.f32x2 %0, %1, %2, %3;" : "=l"(d) : "l"(a), "l"(b), "l"(c)); return d;
}
__device__ __forceinline__ u64 add2_(u64 a, u64 b) {
    u64 d; asm("add.rn.f32x2 %0, %1, %2;" : "=l"(d) : "l"(a), "l"(b)); return d;
}
__device__ __forceinline__ u64 pack2(float x, float y) {
    u64 d; asm("mov.b64 %0, {%1, %2};" : "=l"(d) : "f"(x), "f"(y)); return d;
}
__device__ __forceinline__ float2 unpack2(u64 v) {
    float2 r; asm("mov.b64 {%0, %1}, %2;" : "=f"(r.x), "=f"(r.y) : "l"(v)); return r;
}
__device__ __forceinline__ float ex2f_(float x) {
    float y; asm("ex2.approx.ftz.f32 %0, %1;" : "=f"(y) : "f"(x)); return y;
}

// ============================================================================
// GEMM: out[m,n] = sum_k A[m,k] * W[n,k] + bias[n]
// MODE 0: A = x, three outputs (z selects K/Q/V weights), out layout [B,H,T,hd]
// MODE 1: A = g_Y, out layout [M, C] (final projection into d_out)
// 128x128x16 tiles, 256 threads, 8x8 microtile as f32x2 pairs.
// Both smem tiles k-major with stride 132 (conflict-free LDS.128 fragments).
// ============================================================================
#define TS_ 132   // smem row stride (floats)

template<int MODE>
__global__ void __launch_bounds__(256, 2) gemm_kernel(
    const float* __restrict__ A,
    const float* __restrict__ W0, const float* __restrict__ W1, const float* __restrict__ W2,
    const float* __restrict__ bias0, const float* __restrict__ bias1, const float* __restrict__ bias2,
    float* __restrict__ outp)
{
    __shared__ __align__(16) float As[16 * TS_];
    __shared__ __align__(16) float Bs[16 * TS_];

    const float* W; const float* bias; float* out;
    if (MODE == 0) {
        int z = blockIdx.z;
        W    = (z==0) ? W0    : ((z==1) ? W1    : W2);
        bias = (z==0) ? bias0 : ((z==1) ? bias1 : bias2);
        out  = (z==0) ? g_K   : ((z==1) ? g_Q   : g_V);
    } else {
        W = W0; bias = bias0; out = outp;
    }
    const float* Ap = (MODE == 0) ? A : (const float*)g_Y;

    int tid = threadIdx.x;
    int tx = tid & 15, ty = tid >> 4;
    int m0 = blockIdx.y * 128, n0 = blockIdx.x * 128;

    u64 acc[8][4];
    #pragma unroll
    for (int i = 0; i < 8; i++)
        #pragma unroll
        for (int j = 0; j < 4; j++) acc[i][j] = 0ull;

    // per-thread load coordinates (two 128-row halves)
    int r0_ = tid >> 2,            c4_0 = tid & 3;
    int r1_ = (tid + 256) >> 2,    c4_1 = (tid + 256) & 3;

    float4 fA0, fA1, fW0, fW1;
    fA0 = *(const float4*)&Ap[(m0 + r0_) * C_ + c4_0 * 4];
    fW0 = *(const float4*)&W [(n0 + r0_) * C_ + c4_0 * 4];
    fA1 = *(const float4*)&Ap[(m0 + r1_) * C_ + c4_1 * 4];
    fW1 = *(const float4*)&W [(n0 + r1_) * C_ + c4_1 * 4];

    #pragma unroll 1
    for (int k0 = 0; k0 < C_; k0 += 16) {
        // transpose-store fragments: As[k][m], Bs[k][n]
        As[(c4_0*4+0)*TS_ + r0_] = fA0.x; As[(c4_0*4+1)*TS_ + r0_] = fA0.y;
        As[(c4_0*4+2)*TS_ + r0_] = fA0.z; As[(c4_0*4+3)*TS_ + r0_] = fA0.w;
        Bs[(c4_0*4+0)*TS_ + r0_] = fW0.x; Bs[(c4_0*4+1)*TS_ + r0_] = fW0.y;
        Bs[(c4_0*4+2)*TS_ + r0_] = fW0.z; Bs[(c4_0*4+3)*TS_ + r0_] = fW0.w;
        As[(c4_1*4+0)*TS_ + r1_] = fA1.x; As[(c4_1*4+1)*TS_ + r1_] = fA1.y;
        As[(c4_1*4+2)*TS_ + r1_] = fA1.z; As[(c4_1*4+3)*TS_ + r1_] = fA1.w;
        Bs[(c4_1*4+0)*TS_ + r1_] = fW1.x; Bs[(c4_1*4+1)*TS_ + r1_] = fW1.y;
        Bs[(c4_1*4+2)*TS_ + r1_] = fW1.z; Bs[(c4_1*4+3)*TS_ + r1_] = fW1.w;
        __syncthreads();

        if (k0 + 16 < C_) {
            fA0 = *(const float4*)&Ap[(m0 + r0_) * C_ + k0 + 16 + c4_0 * 4];
            fW0 = *(const float4*)&W [(n0 + r0_) * C_ + k0 + 16 + c4_0 * 4];
            fA1 = *(const float4*)&Ap[(m0 + r1_) * C_ + k0 + 16 + c4_1 * 4];
            fW1 = *(const float4*)&W [(n0 + r1_) * C_ + k0 + 16 + c4_1 * 4];
        }

        #pragma unroll
        for (int k = 0; k < 16; k++) {
            ulonglong2 b01 = *(const ulonglong2*)&Bs[k*TS_ + tx*8];
            ulonglong2 b23 = *(const ulonglong2*)&Bs[k*TS_ + tx*8 + 4];
            float4 a03 = *(const float4*)&As[k*TS_ + ty*8];
            float4 a47 = *(const float4*)&As[k*TS_ + ty*8 + 4];
            float av[8] = {a03.x, a03.y, a03.z, a03.w, a47.x, a47.y, a47.z, a47.w};
            #pragma unroll
            for (int i = 0; i < 8; i++) {
                u64 a2 = pack2(av[i], av[i]);
                acc[i][0] = fma2(a2, b01.x, acc[i][0]);
                acc[i][1] = fma2(a2, b01.y, acc[i][1]);
                acc[i][2] = fma2(a2, b23.x, acc[i][2]);
                acc[i][3] = fma2(a2, b23.y, acc[i][3]);
            }
        }
        __syncthreads();
    }

    int n_base = n0 + tx * 8;
    float4 bb0 = *(const float4*)&bias[n_base];
    float4 bb1 = *(const float4*)&bias[n_base + 4];
    #pragma unroll
    for (int i = 0; i < 8; i++) {
        int mm = m0 + ty*8 + i;
        float* p;
        if (MODE == 0) {
            int bi = mm / T_;
            int tq = mm - bi * T_;
            int h = n_base >> 6, d = n_base & 63;
            p = out + ((((bi * H_) + h) * T_ + tq) << 6) + d;   // [B,H,T,hd]
        } else {
            p = out + (size_t)mm * C_ + n_base;                 // [M,C]
        }
        float2 v0 = unpack2(acc[i][0]), v1 = unpack2(acc[i][1]);
        float2 v2 = unpack2(acc[i][2]), v3 = unpack2(acc[i][3]);
        *(float4*)p       = make_float4(v0.x + bb0.x, v0.y + bb0.y, v1.x + bb0.z, v1.y + bb0.w);
        *(float4*)(p + 4) = make_float4(v2.x + bb1.x, v2.y + bb1.y, v3.x + bb1.z, v3.y + bb1.w);
    }
}

// ============================================================================
// Attention (no-max softmax; mask (q%256) >= (k%256)).
// 256 threads/block. Thread pair (t, t^1): one query row r = s*128 + (t>>1),
// thread half = t&1 owns dims [half*32, half*32+32).
// Keys streamed in 16-key chunks, double-buffered smem, 1 sync/chunk.
// Warp-uniform skip of fully-masked chunks; s=0 blocks run 8 chunks/tile.
// ============================================================================
__device__ __forceinline__ void attn_scores8(
    const float* Kc, int j0, int c0, int r, int half,
    const u64 (&q2)[16], float (&p)[8], float& l)
{
    #pragma unroll
    for (int j = 0; j < 8; j++) {
        const ulonglong2* kr = (const ulonglong2*)(Kc + (j0+j)*64 + half*32);
        u64 a0 = 0ull, a1 = 0ull, a2 = 0ull, a3 = 0ull;
        #pragma unroll
        for (int d = 0; d < 4; d++) {
            ulonglong2 k0_ = kr[2*d];
            ulonglong2 k1_ = kr[2*d+1];
            a0 = fma2(q2[4*d],   k0_.x, a0);
            a1 = fma2(q2[4*d+1], k0_.y, a1);
            a2 = fma2(q2[4*d+2], k1_.x, a2);
            a3 = fma2(q2[4*d+3], k1_.y, a3);
        }
        float2 f = unpack2(add2_(add2_(a0, a1), add2_(a2, a3)));
        float sj = f.x + f.y;
        sj += __shfl_xor_sync(0xffffffffu, sj, 1);
        float pj = (r >= c0 + j0 + j) ? ex2f_(sj) : 0.f;
        p[j] = pj;
        l += pj;
    }
}

__device__ __forceinline__ void attn_av8(
    const float* Vc, int j0, int half, const float (&p)[8], u64 (&acc)[16])
{
    #pragma unroll
    for (int j = 0; j < 8; j++) {
        u64 p2 = pack2(p[j], p[j]);
        const ulonglong2* vr = (const ulonglong2*)(Vc + (j0+j)*64 + half*32);
        #pragma unroll
        for (int d = 0; d < 8; d++) {
            ulonglong2 vv = vr[d];
            acc[2*d]   = fma2(p2, vv.x, acc[2*d]);
            acc[2*d+1] = fma2(p2, vv.y, acc[2*d+1]);
        }
    }
}

__global__ void __launch_bounds__(256, 2) attn_kernel()
{
    __shared__ __align__(16) float Ks[2][16*64];
    __shared__ __align__(16) float Vs[2][16*64];

    const int tid  = threadIdx.x;
    const int bh   = blockIdx.y;             // b*12 + h
    const int ti   = blockIdx.x >> 1;        // tile 0..9
    const int s    = blockIdx.x & 1;         // row half of the tile
    const int half = tid & 1;
    const int r    = s*128 + (tid >> 1);     // row in tile, 0..255
    const int qg   = ti*256 + r;
    const int whi  = s*128 + ((tid >> 5) << 4) + 15;   // max row in this warp
    const int NC   = s ? 16 : 8;             // chunks per key-tile

    const float4* Kb4 = (const float4*)(g_K + (size_t)bh * T_ * HD_);
    const float4* Vb4 = (const float4*)(g_V + (size_t)bh * T_ * HD_);

    const float SC = 0.125f * 1.4426950408889634f;  // (1/sqrt(64)) * log2(e)
    u64 q2[16];
    {
        const float* qp = g_Q + ((size_t)bh * T_ + qg) * HD_ + half * 32;
        #pragma unroll
        for (int i = 0; i < 8; i++) {
            float4 v = *(const float4*)&qp[i*4];
            q2[2*i]   = pack2(v.x*SC, v.y*SC);
            q2[2*i+1] = pack2(v.z*SC, v.w*SC);
        }
    }
    u64 acc[16];
    #pragma unroll
    for (int i = 0; i < 16; i++) acc[i] = 0ull;
    float l = 0.f;

    // preload chunk (kt=0, ci=0): 16 keys x 64 dims = 256 float4 per tensor
    ((float4*)Ks[0])[tid] = Kb4[tid];
    ((float4*)Vs[0])[tid] = Vb4[tid];
    __syncthreads();

    int cb = 0;
    #pragma unroll 1
    for (int kt = 0; kt < 10; kt++) {
        #pragma unroll 1
        for (int ci = 0; ci < NC; ci++) {
            const bool hasNext = !(kt == 9 && ci == NC-1);
            float4 nk, nv;
            if (hasNext) {
                int nkt = (ci == NC-1) ? kt+1 : kt;
                int nci = (ci == NC-1) ? 0    : ci+1;
                int base = (nkt*256 + nci*16) * 16;   // float4 index of chunk start
                nk = Kb4[base + tid];
                nv = Vb4[base + tid];
            }
            const int c0 = ci * 16;
            const float* Kc = Ks[cb];
            const float* Vc = Vs[cb];
            if (c0 <= whi) {       // warp-uniform: some row in warp needs this chunk
                float p[8];
                attn_scores8(Kc, 0, c0, r, half, q2, p, l);
                if (hasNext) { ((float4*)Ks[cb^1])[tid] = nk; ((float4*)Vs[cb^1])[tid] = nv; }
                attn_av8(Vc, 0, half, p, acc);
                attn_scores8(Kc, 8, c0, r, half, q2, p, l);
                attn_av8(Vc, 8, half, p, acc);
            } else {
                if (hasNext) { ((float4*)Ks[cb^1])[tid] = nk; ((float4*)Vs[cb^1])[tid] = nv; }
            }
            __syncthreads();
            cb ^= 1;
        }
    }

    float inv = 1.0f / l;
    int b = bh / H_, h = bh - (bh / H_) * H_;
    float* yp = g_Y + ((size_t)(b * T_ + qg)) * C_ + h * HD_ + half * 32;
    #pragma unroll
    for (int d = 0; d < 8; d++) {
        float2 v0 = unpack2(acc[2*d]), v1 = unpack2(acc[2*d+1]);
        *(float4*)&yp[d*4] = make_float4(v0.x*inv, v0.y*inv, v1.x*inv, v1.y*inv);
    }
}

// ============================================================================
extern "C" void kernel_launch(void* const* d_in, const int* in_sizes, int n_in,
                              void* d_out, int out_size)
{
    (void)in_sizes; (void)n_in; (void)out_size;
    const float* x  = (const float*)d_in[0];
    const float* Wk = (const float*)d_in[1];
    const float* bk = (const float*)d_in[2];
    const float* Wq = (const float*)d_in[3];
    const float* bq = (const float*)d_in[4];
    const float* Wv = (const float*)d_in[5];
    const float* bv = (const float*)d_in[6];
    const float* Wp = (const float*)d_in[7];
    const float* bp = (const float*)d_in[8];
    float* out = (float*)d_out;

    gemm_kernel<0><<<dim3(C_/128, M_/128, 3), 256>>>(x, Wk, Wq, Wv, bk, bq, bv, nullptr);
    attn_kernel<<<dim3(20, B_*H_), 256>>>();
    gemm_kernel<1><<<dim3(C_/128, M_/128, 1), 256>>>(nullptr, Wp, Wp, Wp, bp, bp, bp, out);
}